// round 6
// baseline (speedup 1.0000x reference)
#include <cuda_runtime.h>
#include <cuda_fp16.h>
#include <cstdint>

// Problem: B=8, C=256, H=W=64, O=256, K=3, E=3
// out[b,o,y,x] = sum_{c,t} w2[b,o,t,c] * q[b,c,y+kr-1,x+kc-1]
// w2[b,o,t,c] = fp16( sum_e gates[b,e]*(experts[e,o,c,t]+experts[e,o,c+C,t]) )
// Conv as fp16 mma.sync implicit GEMM, fully cp.async-pipelined:
// q pre-transposed to qT[b][y][x][c] fp16 so staging is a raw byte copy;
// per chunk both A9 (9 tap weight tiles) and Bs (im2col strip) are double-
// buffered and prefetched during the previous chunk's 288-HMMA phase.

#define BQ 8
#define CQ 256
#define HQ 64
#define WQ 64
#define OQ 256

__device__ float  g_yctx[BQ * CQ];
__device__ float  g_gates[BQ * 3];
__device__ __half g_w2[(size_t)BQ * OQ * 2304];          // [b][o][t*256+c]
__device__ __half g_qT[(size_t)BQ * HQ * WQ * CQ];       // [b][y][x][c]

__device__ __forceinline__ uint32_t smem_u32(const void* p) {
    uint32_t a;
    asm("{ .reg .u64 t; cvta.to.shared.u64 t, %1; cvt.u32.u64 %0, t; }" : "=r"(a) : "l"(p));
    return a;
}

// ---------------------------------------------------------------------------
// Kernel 1: global average pool of y -> g_yctx
// ---------------------------------------------------------------------------
__global__ void k_mean(const float* __restrict__ y) {
    int bc = blockIdx.x;
    const float* p = y + (size_t)bc * (HQ * WQ);
    float s = 0.f;
    for (int i = threadIdx.x; i < HQ * WQ; i += 256) s += p[i];
    __shared__ float sm[256];
    sm[threadIdx.x] = s;
    __syncthreads();
    for (int st = 128; st > 0; st >>= 1) {
        if (threadIdx.x < st) sm[threadIdx.x] += sm[threadIdx.x + st];
        __syncthreads();
    }
    if (threadIdx.x == 0) g_yctx[bc] = sm[0] * (1.f / (HQ * WQ));
}

// ---------------------------------------------------------------------------
// Kernel 2: softmax gates
// ---------------------------------------------------------------------------
__global__ void k_gates(const float* __restrict__ gw, const float* __restrict__ gb) {
    int b = blockIdx.x;
    int c = threadIdx.x;
    float v = g_yctx[b * CQ + c];
    float p0 = v * (gw[c * 3 + 0] + gw[(c + CQ) * 3 + 0]);
    float p1 = v * (gw[c * 3 + 1] + gw[(c + CQ) * 3 + 1]);
    float p2 = v * (gw[c * 3 + 2] + gw[(c + CQ) * 3 + 2]);
    __shared__ float sm[3][256];
    sm[0][c] = p0; sm[1][c] = p1; sm[2][c] = p2;
    __syncthreads();
    for (int st = 128; st > 0; st >>= 1) {
        if (c < st) {
            sm[0][c] += sm[0][c + st];
            sm[1][c] += sm[1][c + st];
            sm[2][c] += sm[2][c + st];
        }
        __syncthreads();
    }
    if (c == 0) {
        float l0 = sm[0][0] + gb[0], l1 = sm[1][0] + gb[1], l2 = sm[2][0] + gb[2];
        float m = fmaxf(l0, fmaxf(l1, l2));
        float e0 = expf(l0 - m), e1 = expf(l1 - m), e2 = expf(l2 - m);
        float inv = 1.f / (e0 + e1 + e2);
        g_gates[b * 3 + 0] = e0 * inv;
        g_gates[b * 3 + 1] = e1 * inv;
        g_gates[b * 3 + 2] = e2 * inv;
    }
}

// ---------------------------------------------------------------------------
// Kernel 3: fold experts -> per-batch tap-major fp16 weights
// ---------------------------------------------------------------------------
__global__ void k_fold(const float* __restrict__ experts) {
    int o = blockIdx.x;
    int c = threadIdx.x;
    const size_t ES = (size_t)OQ * (2 * CQ) * 9;
    float f[3][9];
#pragma unroll
    for (int e = 0; e < 3; e++) {
        const float* p = experts + e * ES + (size_t)o * (2 * CQ * 9) + (size_t)c * 9;
#pragma unroll
        for (int t = 0; t < 9; t++) f[e][t] = p[t] + p[CQ * 9 + t];
    }
#pragma unroll
    for (int b = 0; b < BQ; b++) {
        float g0 = g_gates[b * 3 + 0];
        float g1 = g_gates[b * 3 + 1];
        float g2 = g_gates[b * 3 + 2];
        __half* wdst = g_w2 + ((size_t)b * OQ + o) * 2304;
#pragma unroll
        for (int t = 0; t < 9; t++)
            wdst[t * 256 + c] = __float2half_rn(g0 * f[0][t] + g1 * f[1][t] + g2 * f[2][t]);
    }
}

// ---------------------------------------------------------------------------
// Kernel 3b: transpose q -> qT[b][y][x][c] fp16 (c contiguous)
// grid (HQ, BQ); smem tile [64 x][258 c] halves (row 516B: STS conflict-free)
// ---------------------------------------------------------------------------
__global__ __launch_bounds__(256) void k_q16(const float* __restrict__ q) {
    __shared__ __half sm[64][258];
    int yrow = blockIdx.x, b = blockIdx.y;
    const float* src = q + ((size_t)b * CQ) * (HQ * WQ) + yrow * WQ;
    int x  = threadIdx.x & 63;
    int cg = threadIdx.x >> 6;
#pragma unroll
    for (int c0 = 0; c0 < CQ; c0 += 4) {
        int c = c0 + cg;
        sm[x][c] = __float2half_rn(src[(size_t)c * (HQ * WQ) + x]);
    }
    __syncthreads();
    // write out coalesced, 4B words. 64 x * 128 words = 8192 words total.
    uint32_t* dst = (uint32_t*)(g_qT + (((size_t)b * HQ + yrow) * WQ) * CQ);
#pragma unroll
    for (int g = 0; g < 32; g++) {
        int idx = threadIdx.x + g * 256;   // 0..8191
        int xx = idx >> 7;                 // 0..63
        int w  = idx & 127;                // 4B word within row of 256 halves
        dst[xx * 128 + w] = *(const uint32_t*)&sm[xx][w * 2];
    }
}

// ---------------------------------------------------------------------------
// Kernel 4: fp16 mma.sync implicit-GEMM conv, double-buffered cp.async.
// CTA: (b, o-half 128, 2 image rows = 128 px). 8 warps 2(M)x4(N), warp 64x32.
// smem: A9[2][9 t][128 o][80B], Bs[2][264 pos][80B]  = 226560 B, 1 CTA/SM.
// ---------------------------------------------------------------------------
#define A_STRIDE 80
#define A9_BYTES (9 * 128 * A_STRIDE)          // 92160
#define S_STRIDE 80
#define BS_SZ    (264 * S_STRIDE)              // 21120
#define BS_OFF   (2 * A9_BYTES)
#define SM_TOTAL (2 * A9_BYTES + 2 * BS_SZ)    // 226560

__global__ __launch_bounds__(256, 1)
void k_conv(float* __restrict__ out) {
    extern __shared__ __align__(16) unsigned char smc[];
    const uint32_t asBase = smem_u32(smc);
    const uint32_t bsBase = asBase + BS_OFF;

    int tid  = threadIdx.x;
    int lane = tid & 31;
    int warp = tid >> 5;
    int wm   = warp >> 2;
    int wn   = warp & 3;

    int nt = blockIdx.x;        // 0..31
    int o0 = blockIdx.y * 128;
    int b  = blockIdx.z;
    int y0 = nt * 2;

    const __half* qTb = g_qT + (size_t)b * (HQ * WQ * CQ);
    const __half* wb  = g_w2 + ((size_t)b * OQ + o0) * 2304;

    // ---- pre-zero halo cells (never touched by cp.async) ----
    for (int i = tid; i < 2 * 264; i += 256) {
        int buf = i >= 264;
        int pos = buf ? i - 264 : i;
        int r = pos / 66;
        int x = pos - r * 66;
        int gy = y0 - 1 + r;
        bool halo = (x == 0) || (x == 65) || ((unsigned)gy >= (unsigned)HQ);
        if (halo) {
            uint4* d = (uint4*)(smc + BS_OFF + buf * BS_SZ + pos * S_STRIDE);
            uint4 z = make_uint4(0, 0, 0, 0);
            d[0] = z; d[1] = z; d[2] = z; d[3] = z;
        }
    }
    __syncthreads();

    float acc[4][4][4];
#pragma unroll
    for (int i = 0; i < 4; i++)
#pragma unroll
        for (int j = 0; j < 4; j++)
#pragma unroll
            for (int k = 0; k < 4; k++) acc[i][j][k] = 0.f;

    int tg = lane & 3;
    int g8 = lane >> 2;

    // ---- async load of one chunk (A9 + Bs) into buffer `buf` ----
    auto load_chunk = [&](int cc, int buf) {
        int c0 = cc * 32;
        // A9: 18 x 16B per thread
#pragma unroll
        for (int g = 0; g < 18; g++) {
            int idx = tid + g * 256;
            int t   = idx >> 9;
            int rem = idx & 511;
            int o   = rem >> 2;
            int qt  = rem & 3;
            const __half* src = wb + (size_t)o * 2304 + t * 256 + c0 + qt * 8;
            uint32_t dst = asBase + buf * A9_BYTES + (t * 128 + o) * A_STRIDE + qt * 16;
            asm volatile("cp.async.cg.shared.global [%0], [%1], 16;"
                         :: "r"(dst), "l"(src));
        }
        // Bs: interior positions, 4 x 16B each
        for (int pos = tid; pos < 264; pos += 256) {
            int r = pos / 66;
            int x = pos - r * 66;
            int gy = y0 - 1 + r;
            int gx = x - 1;
            if ((unsigned)gy < (unsigned)HQ && (unsigned)gx < (unsigned)WQ) {
                const __half* src = qTb + ((size_t)gy * WQ + gx) * CQ + c0;
                uint32_t dst = bsBase + buf * BS_SZ + pos * S_STRIDE;
#pragma unroll
                for (int seg = 0; seg < 4; seg++)
                    asm volatile("cp.async.cg.shared.global [%0], [%1], 16;"
                                 :: "r"(dst + seg * 16), "l"(src + seg * 8));
            }
        }
        asm volatile("cp.async.commit_group;");
    };

    load_chunk(0, 0);

    for (int cc = 0; cc < 8; cc++) {
        int buf = cc & 1;
        if (cc < 7) load_chunk(cc + 1, buf ^ 1);

        if (cc < 7) asm volatile("cp.async.wait_group 1;");
        else        asm volatile("cp.async.wait_group 0;");
        __syncthreads();   // chunk cc data visible to all warps

        const uint32_t aBuf = asBase + buf * A9_BYTES;
        const unsigned char* BsB = smc + BS_OFF + buf * BS_SZ;

#pragma unroll
        for (int t = 0; t < 9; t++) {
            int kr = t / 3, kc = t - kr * 3;
#pragma unroll
            for (int k16 = 0; k16 < 2; k16++) {
                uint32_t a[4][4];
#pragma unroll
                for (int fm = 0; fm < 4; fm++) {
                    int row = wm * 64 + fm * 16 + (lane & 15);
                    uint32_t addr = aBuf + (t * 128 + row) * A_STRIDE
                                  + ((lane >> 4) << 4) + (k16 << 5);
                    asm volatile(
                        "ldmatrix.sync.aligned.m8n8.x4.shared.b16 {%0,%1,%2,%3}, [%4];"
                        : "=r"(a[fm][0]), "=r"(a[fm][1]), "=r"(a[fm][2]), "=r"(a[fm][3])
                        : "r"(addr));
                }
                uint32_t bf[4][2];
#pragma unroll
                for (int fn = 0; fn < 4; fn++) {
                    int n  = wn * 32 + fn * 8 + g8;
                    int py = n >> 6, px = n & 63;
                    const unsigned char* sp = BsB +
                        ((py + kr) * 66 + px + kc) * S_STRIDE + (k16 << 5) + (tg << 2);
                    bf[fn][0] = *(const uint32_t*)sp;
                    bf[fn][1] = *(const uint32_t*)(sp + 16);
                }
#pragma unroll
                for (int fm = 0; fm < 4; fm++)
#pragma unroll
                    for (int fn = 0; fn < 4; fn++) {
                        asm volatile(
                            "mma.sync.aligned.m16n8k16.row.col.f32.f16.f16.f32 "
                            "{%0,%1,%2,%3}, {%4,%5,%6,%7}, {%8,%9}, {%0,%1,%2,%3};"
                            : "+f"(acc[fm][fn][0]), "+f"(acc[fm][fn][1]),
                              "+f"(acc[fm][fn][2]), "+f"(acc[fm][fn][3])
                            : "r"(a[fm][0]), "r"(a[fm][1]), "r"(a[fm][2]), "r"(a[fm][3]),
                              "r"(bf[fn][0]), "r"(bf[fn][1]));
                    }
            }
        }
        __syncthreads();   // all warps done reading buf before it is refilled
    }

    // ---- epilogue ----
#pragma unroll
    for (int fm = 0; fm < 4; fm++)
#pragma unroll
        for (int fn = 0; fn < 4; fn++) {
            int o  = o0 + wm * 64 + fm * 16 + g8;
            int n  = wn * 32 + fn * 8 + tg * 2;
            int py = n >> 6, px = n & 63;
            float* dst = out + (((size_t)(b * OQ + o)) * HQ + y0 + py) * WQ + px;
            *(float2*)dst = make_float2(acc[fm][fn][0], acc[fm][fn][1]);
            *(float2*)(dst + 8 * HQ * WQ) = make_float2(acc[fm][fn][2], acc[fm][fn][3]);
        }
}

// ---------------------------------------------------------------------------
extern "C" void kernel_launch(void* const* d_in, const int* in_sizes, int n_in,
                              void* d_out, int out_size) {
    const float* q       = (const float*)d_in[0];
    const float* y       = (const float*)d_in[1];
    const float* experts = (const float*)d_in[2];
    const float* gate_w  = (const float*)d_in[3];
    const float* gate_b  = (const float*)d_in[4];
    float* out = (float*)d_out;

    cudaFuncSetAttribute(k_conv, cudaFuncAttributeMaxDynamicSharedMemorySize, SM_TOTAL);

    k_mean<<<BQ * CQ, 256>>>(y);
    k_gates<<<BQ, 256>>>(gate_w, gate_b);
    k_fold<<<OQ, 256>>>(experts);
    k_q16<<<dim3(HQ, BQ), 256>>>(q);

    dim3 grid(32, 2, BQ);   // 512 CTAs, 1/SM
    k_conv<<<grid, 256, SM_TOTAL>>>(out);
}

// round 7
// speedup vs baseline: 1.1540x; 1.1540x over previous
#include <cuda_runtime.h>
#include <cuda_fp16.h>
#include <cstdint>

// Problem: B=8, C=256, H=W=64, O=256, K=3, E=3
// out[b,o,y,x] = sum_{c,t} w2[b,o,t,c] * q[b,c,y+kr-1,x+kc-1]
// Conv as fp16 mma.sync implicit GEMM. 24-stage cp.async pipeline
// (8 c-chunks x 3 kernel-rows), dense 64B-stride smem tiles with XOR-unit
// swizzle (conflict-free), double-buffered, 2 CTAs/SM.

#define BQ 8
#define CQ 256
#define HQ 64
#define WQ 64
#define OQ 256

__device__ float  g_yctx[BQ * CQ];
__device__ float  g_gates[BQ * 3];
__device__ __half g_w2[(size_t)BQ * OQ * 2304];          // [b][o][t*256+c]
__device__ __half g_qT[(size_t)BQ * HQ * WQ * CQ];       // [b][y][x][c]

__device__ __forceinline__ uint32_t smem_u32(const void* p) {
    uint32_t a;
    asm("{ .reg .u64 t; cvta.to.shared.u64 t, %1; cvt.u32.u64 %0, t; }" : "=r"(a) : "l"(p));
    return a;
}

// ---------------------------------------------------------------------------
// Kernel 1: global average pool of y -> g_yctx
// ---------------------------------------------------------------------------
__global__ void k_mean(const float* __restrict__ y) {
    int bc = blockIdx.x;
    const float* p = y + (size_t)bc * (HQ * WQ);
    float s = 0.f;
    for (int i = threadIdx.x; i < HQ * WQ; i += 256) s += p[i];
    __shared__ float sm[256];
    sm[threadIdx.x] = s;
    __syncthreads();
    for (int st = 128; st > 0; st >>= 1) {
        if (threadIdx.x < st) sm[threadIdx.x] += sm[threadIdx.x + st];
        __syncthreads();
    }
    if (threadIdx.x == 0) g_yctx[bc] = sm[0] * (1.f / (HQ * WQ));
}

// ---------------------------------------------------------------------------
// Kernel 2: softmax gates
// ---------------------------------------------------------------------------
__global__ void k_gates(const float* __restrict__ gw, const float* __restrict__ gb) {
    int b = blockIdx.x;
    int c = threadIdx.x;
    float v = g_yctx[b * CQ + c];
    float p0 = v * (gw[c * 3 + 0] + gw[(c + CQ) * 3 + 0]);
    float p1 = v * (gw[c * 3 + 1] + gw[(c + CQ) * 3 + 1]);
    float p2 = v * (gw[c * 3 + 2] + gw[(c + CQ) * 3 + 2]);
    __shared__ float sm[3][256];
    sm[0][c] = p0; sm[1][c] = p1; sm[2][c] = p2;
    __syncthreads();
    for (int st = 128; st > 0; st >>= 1) {
        if (c < st) {
            sm[0][c] += sm[0][c + st];
            sm[1][c] += sm[1][c + st];
            sm[2][c] += sm[2][c + st];
        }
        __syncthreads();
    }
    if (c == 0) {
        float l0 = sm[0][0] + gb[0], l1 = sm[1][0] + gb[1], l2 = sm[2][0] + gb[2];
        float m = fmaxf(l0, fmaxf(l1, l2));
        float e0 = expf(l0 - m), e1 = expf(l1 - m), e2 = expf(l2 - m);
        float inv = 1.f / (e0 + e1 + e2);
        g_gates[b * 3 + 0] = e0 * inv;
        g_gates[b * 3 + 1] = e1 * inv;
        g_gates[b * 3 + 2] = e2 * inv;
    }
}

// ---------------------------------------------------------------------------
// Kernel 3: fold experts -> per-batch tap-major fp16 weights
// ---------------------------------------------------------------------------
__global__ void k_fold(const float* __restrict__ experts) {
    int o = blockIdx.x;
    int c = threadIdx.x;
    const size_t ES = (size_t)OQ * (2 * CQ) * 9;
    float f[3][9];
#pragma unroll
    for (int e = 0; e < 3; e++) {
        const float* p = experts + e * ES + (size_t)o * (2 * CQ * 9) + (size_t)c * 9;
#pragma unroll
        for (int t = 0; t < 9; t++) f[e][t] = p[t] + p[CQ * 9 + t];
    }
#pragma unroll
    for (int b = 0; b < BQ; b++) {
        float g0 = g_gates[b * 3 + 0];
        float g1 = g_gates[b * 3 + 1];
        float g2 = g_gates[b * 3 + 2];
        __half* wdst = g_w2 + ((size_t)b * OQ + o) * 2304;
#pragma unroll
        for (int t = 0; t < 9; t++)
            wdst[t * 256 + c] = __float2half_rn(g0 * f[0][t] + g1 * f[1][t] + g2 * f[2][t]);
    }
}

// ---------------------------------------------------------------------------
// Kernel 3b: transpose q -> qT[b][y][x][c] fp16 (c contiguous)
// ---------------------------------------------------------------------------
__global__ __launch_bounds__(256) void k_q16(const float* __restrict__ q) {
    __shared__ __half sm[64][258];
    int yrow = blockIdx.x, b = blockIdx.y;
    const float* src = q + ((size_t)b * CQ) * (HQ * WQ) + yrow * WQ;
    int x  = threadIdx.x & 63;
    int cg = threadIdx.x >> 6;
#pragma unroll
    for (int c0 = 0; c0 < CQ; c0 += 4) {
        int c = c0 + cg;
        sm[x][c] = __float2half_rn(src[(size_t)c * (HQ * WQ) + x]);
    }
    __syncthreads();
    uint32_t* dst = (uint32_t*)(g_qT + (((size_t)b * HQ + yrow) * WQ) * CQ);
#pragma unroll
    for (int g = 0; g < 32; g++) {
        int idx = threadIdx.x + g * 256;   // 0..8191
        int xx = idx >> 7;
        int w  = idx & 127;
        dst[xx * 128 + w] = *(const uint32_t*)&sm[xx][w * 2];
    }
}

// ---------------------------------------------------------------------------
// Kernel 4: fp16 mma.sync implicit-GEMM conv, 24-stage pipeline, 2 CTAs/SM.
// CTA: (b, o-half 128, 2 image rows = 128 px). 8 warps 2(M)x4(N), warp 64x32.
// Tiles dense 64B rows, swizzle: phys16Bunit = u ^ ((row>>1)&3).
// A3[2][3 kc][128 o][64B] = 2x24576, Bs[2][264 pos][64B] = 2x16896 -> 82944B.
// ---------------------------------------------------------------------------
#define A3_SZ  (3 * 128 * 64)       // 24576
#define BS_SZ  (264 * 64)           // 16896
#define BS_OFF (2 * A3_SZ)          // 49152
#define SM_TOTAL (2 * A3_SZ + 2 * BS_SZ)   // 82944

__global__ __launch_bounds__(256, 2)
void k_conv(float* __restrict__ out) {
    extern __shared__ __align__(16) unsigned char smc[];
    const uint32_t asBase = smem_u32(smc);
    const uint32_t bsBase = asBase + BS_OFF;

    int tid  = threadIdx.x;
    int lane = tid & 31;
    int warp = tid >> 5;
    int wm   = warp >> 2;
    int wn   = warp & 3;

    int nt = blockIdx.x;        // 0..31
    int o0 = blockIdx.y * 128;
    int b  = blockIdx.z;
    int y0 = nt * 2;

    const __half* qTb = g_qT + (size_t)b * (HQ * WQ * CQ);
    const __half* wb  = g_w2 + ((size_t)b * OQ + o0) * 2304;

    // ---- pre-zero halo positions in both Bs buffers ----
    for (int i = tid; i < 2 * 264; i += 256) {
        int bb  = i >= 264;
        int pos = bb ? i - 264 : i;
        int r = pos / 66;
        int x = pos - r * 66;
        int gy = y0 - 1 + r;
        if ((x == 0) | (x == 65) | ((unsigned)gy >= (unsigned)HQ)) {
            uint4* d = (uint4*)(smc + BS_OFF + bb * BS_SZ + pos * 64);
            uint4 z = make_uint4(0, 0, 0, 0);
            d[0] = z; d[1] = z; d[2] = z; d[3] = z;
        }
    }
    __syncthreads();

    float acc[4][4][4];
#pragma unroll
    for (int i = 0; i < 4; i++)
#pragma unroll
        for (int j = 0; j < 4; j++)
#pragma unroll
            for (int k = 0; k < 4; k++) acc[i][j][k] = 0.f;

    int tg = lane & 3;
    int g8 = lane >> 2;

    // ---- async prefetch of stage s = (cc, kr) ----
    auto load_stage = [&](int s) {
        int cc = s / 3, kr = s - cc * 3;
        int abuf = s & 1;
        int c0 = cc * 32;
        // A3: 6 x 16B units per thread (3*128*4 = 1536 units)
#pragma unroll
        for (int g = 0; g < 6; g++) {
            int idx = tid + g * 256;
            int kc  = idx >> 9;
            int rem = idx & 511;
            int o   = rem >> 2;
            int u   = rem & 3;
            const __half* src = wb + (size_t)o * 2304 + (kr * 3 + kc) * 256 + c0 + u * 8;
            int phys = u ^ ((o >> 1) & 3);
            uint32_t dst = asBase + abuf * A3_SZ + (kc * 128 + o) * 64 + phys * 16;
            asm volatile("cp.async.cg.shared.global [%0], [%1], 16;"
                         :: "r"(dst), "l"(src));
        }
        // Bs: once per chunk (kr == 0)
        if (kr == 0) {
            int bbuf = cc & 1;
            for (int i = tid; i < 1056; i += 256) {
                int pos = i >> 2;
                int u   = i & 3;
                int r = pos / 66;
                int x = pos - r * 66;
                int gy = y0 - 1 + r;
                int gx = x - 1;
                if ((unsigned)gy < (unsigned)HQ && (unsigned)gx < (unsigned)WQ) {
                    const __half* src = qTb + ((size_t)gy * WQ + gx) * CQ + c0 + u * 8;
                    int phys = u ^ ((pos >> 1) & 3);
                    uint32_t dst = bsBase + bbuf * BS_SZ + pos * 64 + phys * 16;
                    asm volatile("cp.async.cg.shared.global [%0], [%1], 16;"
                                 :: "r"(dst), "l"(src));
                }
            }
        }
        asm volatile("cp.async.commit_group;");
    };

    load_stage(0);

    for (int s = 0; s < 24; s++) {
        if (s < 23) load_stage(s + 1);
        if (s < 23) asm volatile("cp.async.wait_group 1;");
        else        asm volatile("cp.async.wait_group 0;");
        __syncthreads();   // stage s data visible

        int cc = s / 3, kr = s - cc * 3;
        const uint32_t aBuf = asBase + (s & 1) * A3_SZ;
        const uint32_t bBuf = bsBase + (cc & 1) * BS_SZ;

#pragma unroll
        for (int kc = 0; kc < 3; kc++) {
#pragma unroll
            for (int k16 = 0; k16 < 2; k16++) {
                uint32_t a[4][4];
#pragma unroll
                for (int fm = 0; fm < 4; fm++) {
                    int row = wm * 64 + fm * 16 + (lane & 15);
                    int u   = (lane >> 4) + 2 * k16;
                    int phys = u ^ ((row >> 1) & 3);
                    uint32_t addr = aBuf + (kc * 128 + row) * 64 + phys * 16;
                    asm volatile(
                        "ldmatrix.sync.aligned.m8n8.x4.shared.b16 {%0,%1,%2,%3}, [%4];"
                        : "=r"(a[fm][0]), "=r"(a[fm][1]), "=r"(a[fm][2]), "=r"(a[fm][3])
                        : "r"(addr));
                }
                uint32_t bf[4][2];
#pragma unroll
                for (int fn = 0; fn < 4; fn++) {
                    int n  = wn * 32 + fn * 8 + g8;
                    int py = n >> 6, px = n & 63;
                    int pos = (py + kr) * 66 + px + kc;
                    int sw  = (pos >> 1) & 3;
                    uint32_t base = bBuf + pos * 64 + tg * 4;
                    uint32_t a0 = base + ((2 * k16) ^ sw) * 16;
                    uint32_t a1 = base + ((2 * k16 + 1) ^ sw) * 16;
                    asm volatile("ld.shared.b32 %0, [%1];" : "=r"(bf[fn][0]) : "r"(a0));
                    asm volatile("ld.shared.b32 %0, [%1];" : "=r"(bf[fn][1]) : "r"(a1));
                }
#pragma unroll
                for (int fm = 0; fm < 4; fm++)
#pragma unroll
                    for (int fn = 0; fn < 4; fn++) {
                        asm volatile(
                            "mma.sync.aligned.m16n8k16.row.col.f32.f16.f16.f32 "
                            "{%0,%1,%2,%3}, {%4,%5,%6,%7}, {%8,%9}, {%0,%1,%2,%3};"
                            : "+f"(acc[fm][fn][0]), "+f"(acc[fm][fn][1]),
                              "+f"(acc[fm][fn][2]), "+f"(acc[fm][fn][3])
                            : "r"(a[fm][0]), "r"(a[fm][1]), "r"(a[fm][2]), "r"(a[fm][3]),
                              "r"(bf[fn][0]), "r"(bf[fn][1]));
                    }
            }
        }
        __syncthreads();   // all warps done with stage s buffers
    }

    // ---- epilogue ----
#pragma unroll
    for (int fm = 0; fm < 4; fm++)
#pragma unroll
        for (int fn = 0; fn < 4; fn++) {
            int o  = o0 + wm * 64 + fm * 16 + g8;
            int n  = wn * 32 + fn * 8 + tg * 2;
            int py = n >> 6, px = n & 63;
            float* dst = out + (((size_t)(b * OQ + o)) * HQ + y0 + py) * WQ + px;
            *(float2*)dst = make_float2(acc[fm][fn][0], acc[fm][fn][1]);
            *(float2*)(dst + 8 * HQ * WQ) = make_float2(acc[fm][fn][2], acc[fm][fn][3]);
        }
}

// ---------------------------------------------------------------------------
extern "C" void kernel_launch(void* const* d_in, const int* in_sizes, int n_in,
                              void* d_out, int out_size) {
    const float* q       = (const float*)d_in[0];
    const float* y       = (const float*)d_in[1];
    const float* experts = (const float*)d_in[2];
    const float* gate_w  = (const float*)d_in[3];
    const float* gate_b  = (const float*)d_in[4];
    float* out = (float*)d_out;

    cudaFuncSetAttribute(k_conv, cudaFuncAttributeMaxDynamicSharedMemorySize, SM_TOTAL);

    k_mean<<<BQ * CQ, 256>>>(y);
    k_gates<<<BQ, 256>>>(gate_w, gate_b);
    k_fold<<<OQ, 256>>>(experts);
    k_q16<<<dim3(HQ, BQ), 256>>>(q);

    dim3 grid(32, 2, BQ);   // 512 CTAs, 2/SM
    k_conv<<<grid, 256, SM_TOTAL>>>(out);
}